// round 1
// baseline (speedup 1.0000x reference)
#include <cuda_runtime.h>
#include <math.h>

// Problem constants
#define BATCH 2
#define CC    128
#define HH    64
#define WW    64
#define HW    4096           // H*W
#define NPIX  8192           // B*H*W
#define NCLS  4
#define KSEL  50
#define NBIN  1024
#define MAXCAND 2048
// exp(x/tau) = exp2f(x * log2(e)/0.07)
#define TAUINV_LOG2E 20.6099291555566197f

// ---------------- device scratch (no allocations allowed) ----------------
__device__ float4 g_inT4[NPIX * 32];     // normalized input,   [N][128] as float4[N][32]
__device__ float4 g_posT4[NPIX * 32];    // normalized positive
__device__ float  g_pos_sim[NPIX];
__device__ int    g_seg_in[NPIX];
__device__ int    g_seg_neg[NPIX];
__device__ float  g_neg_prob[NPIX];
__device__ int    g_sel[NCLS][KSEL];
__device__ float4 g_G4[NCLS * KSEL * 32]; // normalized selected negatives [4][50][128]
__device__ float  g_acc;

// ---------------- kernel 0: zero accumulator ----------------
__global__ void k_zero() { g_acc = 0.0f; }

// ---------------- kernel 1: seg / prob from 4-class logits ----------------
__global__ void k_seg(const float* __restrict__ il, const float* __restrict__ nl) {
    int n = blockIdx.x * 256 + threadIdx.x;
    if (n >= NPIX) return;
    int b = n >> 12, rem = n & 4095;

    const float* pi = il + (size_t)b * NCLS * HW + rem;
    float l0 = pi[0], l1 = pi[HW], l2 = pi[2 * HW], l3 = pi[3 * HW];
    int amax = 0; float m = l0;
    if (l1 > m) { m = l1; amax = 1; }
    if (l2 > m) { m = l2; amax = 2; }
    if (l3 > m) { m = l3; amax = 3; }
    g_seg_in[n] = amax;

    const float* pn = nl + (size_t)b * NCLS * HW + rem;
    l0 = pn[0]; l1 = pn[HW]; l2 = pn[2 * HW]; l3 = pn[3 * HW];
    amax = 0; m = l0;
    if (l1 > m) { m = l1; amax = 1; }
    if (l2 > m) { m = l2; amax = 2; }
    if (l3 > m) { m = l3; amax = 3; }
    float s = __expf(l0 - m) + __expf(l1 - m) + __expf(l2 - m) + __expf(l3 - m);
    g_seg_neg[n]  = amax;
    g_neg_prob[n] = 1.0f / s;   // max softmax prob = exp(0)/sum(exp(l-k))
}

// ---------------- kernel 2: normalize+transpose input/positive, pos_sim ----------------
// block = 256 threads handles 32 consecutive pixels; grid = 256 blocks.
__global__ void k_norm(const float* __restrict__ inp, const float* __restrict__ pos) {
    __shared__ float s_in[CC * 33];       // [c][p], pad 33 to kill bank conflicts
    __shared__ float s_po[CC * 33];
    __shared__ float s_red[3 * 8 * 32];   // partial sums [3][g][p]
    __shared__ float s_invi[32], s_invp[32];

    int t = threadIdx.x;
    int base = blockIdx.x * 32;           // first pixel of this block
    int b = base >> 12, rem0 = base & 4095;

    // cooperative coalesced load: idx = i*256 + t ; c = idx>>5 ; p = idx&31
    #pragma unroll
    for (int i = 0; i < 16; i++) {
        int idx = i * 256 + t;
        int c = idx >> 5, p = idx & 31;
        size_t g = (size_t)(b * CC + c) * HW + rem0 + p;
        s_in[c * 33 + p] = inp[g];
        s_po[c * 33 + p] = pos[g];
    }
    __syncthreads();

    // partial reductions: 8 channel-groups x 32 pixels
    {
        int g = t >> 5, p = t & 31;
        float ssi = 0.f, ssp = 0.f, dp = 0.f;
        #pragma unroll
        for (int j = 0; j < 16; j++) {
            int c = g * 16 + j;
            float a = s_in[c * 33 + p];
            float q = s_po[c * 33 + p];
            ssi += a * a; ssp += q * q; dp += a * q;
        }
        s_red[(0 * 8 + g) * 32 + p] = ssi;
        s_red[(1 * 8 + g) * 32 + p] = ssp;
        s_red[(2 * 8 + g) * 32 + p] = dp;
    }
    __syncthreads();

    if (t < 32) {
        int p = t;
        float ssi = 0.f, ssp = 0.f, dp = 0.f;
        #pragma unroll
        for (int g = 0; g < 8; g++) {
            ssi += s_red[(0 * 8 + g) * 32 + p];
            ssp += s_red[(1 * 8 + g) * 32 + p];
            dp  += s_red[(2 * 8 + g) * 32 + p];
        }
        float invi = 1.0f / fmaxf(sqrtf(ssi), 1e-12f);
        float invp = 1.0f / fmaxf(sqrtf(ssp), 1e-12f);
        s_invi[p] = invi;
        s_invp[p] = invp;
        g_pos_sim[base + p] = dp * invi * invp;
    }
    __syncthreads();

    // write normalized, transposed: warp w handles pixels w*4..w*4+3, lanes over channels
    {
        int w = t >> 5, lane = t & 31;
        float* oi = (float*)g_inT4;
        float* op = (float*)g_posT4;
        #pragma unroll
        for (int j = 0; j < 4; j++) {
            int p = w * 4 + j;
            float invi = s_invi[p], invp = s_invp[p];
            size_t row = (size_t)(base + p) * CC;
            #pragma unroll
            for (int ch = 0; ch < 4; ch++) {
                int c = ch * 32 + lane;
                oi[row + c] = s_in[c * 33 + p] * invi;
                op[row + c] = s_po[c * 33 + p] * invp;
            }
        }
    }
}

// ---------------- kernel 3: per-class top-50 selection ----------------
// 4 blocks (one per class), 256 threads.
__global__ void k_select() {
    __shared__ int   hist[NBIN];
    __shared__ int   s_chunk[32];
    __shared__ float cv[MAXCAND];
    __shared__ int   ci[MAXCAND];
    __shared__ int   s_cnt;
    __shared__ int   s_binThr;

    int s = blockIdx.x;
    int t = threadIdx.x;

    for (int i = t; i < NBIN; i += 256) hist[i] = 0;
    if (t == 0) s_cnt = 0;
    __syncthreads();

    // histogram of masked values (zero-mask entries excluded; they never reach top-50)
    for (int i = t; i < NPIX; i += 256) {
        if (g_seg_neg[i] != s) {
            float v = g_neg_prob[i];                       // in [0.25, 1)
            int bin = (int)((v - 0.25f) * (1024.0f / 0.75f));
            bin = max(0, min(NBIN - 1, bin));
            atomicAdd(&hist[bin], 1);
        }
    }
    __syncthreads();

    // coarse suffix sums: 32 chunks of 32 bins
    if (t < 32) {
        int sum = 0;
        #pragma unroll
        for (int j = 0; j < 32; j++) sum += hist[t * 32 + j];
        s_chunk[t] = sum;
    }
    __syncthreads();

    if (t == 0) {
        int cum = 0, binThr = 0;
        for (int cb = 31; cb >= 0; cb--) {
            if (cum + s_chunk[cb] >= KSEL) {
                for (int bb = cb * 32 + 31; bb >= cb * 32; bb--) {
                    cum += hist[bb];
                    if (cum >= KSEL) { binThr = bb; break; }
                }
                break;
            }
            cum += s_chunk[cb];
        }
        s_binThr = binThr;
    }
    __syncthreads();
    int binThr = s_binThr;

    // collect candidates: everything in bin >= binThr (superset of global top-50)
    for (int i = t; i < NPIX; i += 256) {
        if (g_seg_neg[i] != s) {
            float v = g_neg_prob[i];
            int bin = (int)((v - 0.25f) * (1024.0f / 0.75f));
            bin = max(0, min(NBIN - 1, bin));
            if (bin >= binThr) {
                int pos = atomicAdd(&s_cnt, 1);
                if (pos < MAXCAND) { cv[pos] = v; ci[pos] = i; }
            }
        }
    }
    __syncthreads();
    int M = min(s_cnt, MAXCAND);

    // exact rank within candidates (value desc, index asc tie-break == lax.top_k)
    for (int c = t; c < M; c += 256) {
        float v = cv[c]; int id = ci[c];
        int r = 0;
        for (int m = 0; m < M; m++) {
            float vm = cv[m];
            if (vm > v || (vm == v && ci[m] < id)) r++;
        }
        if (r < KSEL) g_sel[s][r] = id;
    }
}

// ---------------- kernel 4: gather+normalize the 200 selected negatives ----------------
__global__ void k_gather(const float* __restrict__ neg) {
    int w = (blockIdx.x * blockDim.x + threadIdx.x) >> 5;
    int lane = threadIdx.x & 31;
    if (w >= NCLS * KSEL) return;
    int s = w / KSEL, k = w % KSEL;
    int n = g_sel[s][k];
    int b = n >> 12, rem = n & 4095;
    const float* p = neg + (size_t)b * CC * HW + rem;

    float v[4]; float ss = 0.f;
    #pragma unroll
    for (int j = 0; j < 4; j++) {
        int c = lane + j * 32;
        v[j] = p[(size_t)c * HW];
        ss += v[j] * v[j];
    }
    #pragma unroll
    for (int off = 16; off; off >>= 1) ss += __shfl_xor_sync(0xffffffffu, ss, off);
    float inv = 1.0f / fmaxf(sqrtf(ss), 1e-12f);

    float* G = (float*)g_G4;
    size_t row = (size_t)(s * KSEL + k) * CC;
    #pragma unroll
    for (int j = 0; j < 4; j++) {
        int c = lane + j * 32;
        G[row + c] = v[j] * inv;
    }
}

// ---------------- kernel 5: main contrastive accumulation ----------------
// warp per pixel; 1024 blocks x 256 threads = 8192 warps.
__global__ void k_main() {
    int warp = threadIdx.x >> 5, lane = threadIdx.x & 31;
    int n = blockIdx.x * 8 + warp;

    float4 x4 = g_inT4[(size_t)n * 32 + lane];
    float4 p4 = g_posT4[(size_t)n * 32 + lane];
    int cls = g_seg_in[n];
    const float4* G = g_G4 + (size_t)cls * KSEL * 32;

    float accN = 0.f, accA = 0.f;
    #pragma unroll 5
    for (int k = 0; k < KSEL; k++) {
        float4 g4 = __ldg(&G[(size_t)k * 32 + lane]);
        float dn = g4.x * x4.x + g4.y * x4.y + g4.z * x4.z + g4.w * x4.w;
        float da = g4.x * p4.x + g4.y * p4.y + g4.z * p4.z + g4.w * p4.w;
        #pragma unroll
        for (int off = 16; off; off >>= 1) {
            dn += __shfl_xor_sync(0xffffffffu, dn, off);
            da += __shfl_xor_sync(0xffffffffu, da, off);
        }
        accN += exp2f(dn * TAUINV_LOG2E);
        accA += exp2f(da * TAUINV_LOG2E);
    }

    float ps  = g_pos_sim[n];
    float nom = exp2f(ps * TAUINV_LOG2E);
    float term = logf(nom / (accN + nom + 1e-8f)) + logf(nom / (accA + nom + 1e-8f));

    __shared__ float sred[8];
    if (lane == 0) sred[warp] = term;
    __syncthreads();
    if (threadIdx.x == 0) {
        float sum = 0.f;
        #pragma unroll
        for (int i = 0; i < 8; i++) sum += sred[i];
        atomicAdd(&g_acc, sum);
    }
}

// ---------------- kernel 6: finalize ----------------
__global__ void k_final(float* __restrict__ out) {
    out[0] = -g_acc / (float)NPIX;
}

// ---------------- launch ----------------
extern "C" void kernel_launch(void* const* d_in, const int* in_sizes, int n_in,
                              void* d_out, int out_size) {
    const float* inp = (const float*)d_in[0];   // input    [2,128,64,64]
    const float* pos = (const float*)d_in[1];   // positive
    const float* neg = (const float*)d_in[2];   // negative
    const float* il  = (const float*)d_in[3];   // input_logits    [2,4,64,64]
    const float* nl  = (const float*)d_in[4];   // negative_logits
    float* out = (float*)d_out;

    k_zero<<<1, 1>>>();
    k_seg<<<NPIX / 256, 256>>>(il, nl);
    k_norm<<<NPIX / 32, 256>>>(inp, pos);
    k_select<<<NCLS, 256>>>();
    k_gather<<<(NCLS * KSEL * 32 + 255) / 256, 256>>>(neg);
    k_main<<<NPIX / 8, 256>>>();
    k_final<<<1, 1>>>(out);
}

// round 2
// speedup vs baseline: 1.2528x; 1.2528x over previous
#include <cuda_runtime.h>
#include <math.h>

// Problem constants
#define BATCH 2
#define CC    128
#define HW    4096           // H*W
#define NPIX  8192           // B*H*W
#define NCLS  4
#define KSEL  50
#define NBIN  1024
#define MAXCAND 2048
// exp(x/tau) = exp2f(x * log2(e)/0.07)
#define TAUINV_LOG2E 20.6099291555566197f

// ---------------- device scratch (no allocations allowed) ----------------
__device__ float4 g_inT4[NPIX * 32];     // normalized input,   [N][128] as float4[N][32]
__device__ float4 g_posT4[NPIX * 32];    // normalized positive
__device__ float  g_pos_sim[NPIX];
__device__ int    g_seg_in[NPIX];
__device__ int    g_seg_neg[NPIX];
__device__ float  g_neg_prob[NPIX];
__device__ float4 g_G4[NCLS * KSEL * 32]; // normalized selected negatives [4][50][128]
__device__ float  g_acc;

// ---------------- kernel 1: seg / prob from 4-class logits (+zero acc) ----------------
__global__ void k_seg(const float* __restrict__ il, const float* __restrict__ nl) {
    int n = blockIdx.x * 256 + threadIdx.x;
    if (n == 0) g_acc = 0.0f;
    if (n >= NPIX) return;
    int b = n >> 12, rem = n & 4095;

    const float* pi = il + (size_t)b * NCLS * HW + rem;
    float l0 = pi[0], l1 = pi[HW], l2 = pi[2 * HW], l3 = pi[3 * HW];
    int amax = 0; float m = l0;
    if (l1 > m) { m = l1; amax = 1; }
    if (l2 > m) { m = l2; amax = 2; }
    if (l3 > m) { m = l3; amax = 3; }
    g_seg_in[n] = amax;

    const float* pn = nl + (size_t)b * NCLS * HW + rem;
    l0 = pn[0]; l1 = pn[HW]; l2 = pn[2 * HW]; l3 = pn[3 * HW];
    amax = 0; m = l0;
    if (l1 > m) { m = l1; amax = 1; }
    if (l2 > m) { m = l2; amax = 2; }
    if (l3 > m) { m = l3; amax = 3; }
    float s = __expf(l0 - m) + __expf(l1 - m) + __expf(l2 - m) + __expf(l3 - m);
    g_seg_neg[n]  = amax;
    g_neg_prob[n] = 1.0f / s;   // max softmax prob
}

// ---------------- kernel 2: normalize+transpose input/positive, pos_sim ----------------
__global__ void k_norm(const float* __restrict__ inp, const float* __restrict__ pos) {
    __shared__ float s_in[CC * 33];
    __shared__ float s_po[CC * 33];
    __shared__ float s_red[3 * 8 * 32];
    __shared__ float s_invi[32], s_invp[32];

    int t = threadIdx.x;
    int base = blockIdx.x * 32;
    int b = base >> 12, rem0 = base & 4095;

    #pragma unroll
    for (int i = 0; i < 16; i++) {
        int idx = i * 256 + t;
        int c = idx >> 5, p = idx & 31;
        size_t g = (size_t)(b * CC + c) * HW + rem0 + p;
        s_in[c * 33 + p] = inp[g];
        s_po[c * 33 + p] = pos[g];
    }
    __syncthreads();

    {
        int g = t >> 5, p = t & 31;
        float ssi = 0.f, ssp = 0.f, dp = 0.f;
        #pragma unroll
        for (int j = 0; j < 16; j++) {
            int c = g * 16 + j;
            float a = s_in[c * 33 + p];
            float q = s_po[c * 33 + p];
            ssi += a * a; ssp += q * q; dp += a * q;
        }
        s_red[(0 * 8 + g) * 32 + p] = ssi;
        s_red[(1 * 8 + g) * 32 + p] = ssp;
        s_red[(2 * 8 + g) * 32 + p] = dp;
    }
    __syncthreads();

    if (t < 32) {
        int p = t;
        float ssi = 0.f, ssp = 0.f, dp = 0.f;
        #pragma unroll
        for (int g = 0; g < 8; g++) {
            ssi += s_red[(0 * 8 + g) * 32 + p];
            ssp += s_red[(1 * 8 + g) * 32 + p];
            dp  += s_red[(2 * 8 + g) * 32 + p];
        }
        float invi = 1.0f / fmaxf(sqrtf(ssi), 1e-12f);
        float invp = 1.0f / fmaxf(sqrtf(ssp), 1e-12f);
        s_invi[p] = invi;
        s_invp[p] = invp;
        g_pos_sim[base + p] = dp * invi * invp;
    }
    __syncthreads();

    {
        int w = t >> 5, lane = t & 31;
        float* oi = (float*)g_inT4;
        float* op = (float*)g_posT4;
        #pragma unroll
        for (int j = 0; j < 4; j++) {
            int p = w * 4 + j;
            float invi = s_invi[p], invp = s_invp[p];
            size_t row = (size_t)(base + p) * CC;
            #pragma unroll
            for (int ch = 0; ch < 4; ch++) {
                int c = ch * 32 + lane;
                oi[row + c] = s_in[c * 33 + p] * invi;
                op[row + c] = s_po[c * 33 + p] * invp;
            }
        }
    }
}

// ---------------- kernel 3: per-class top-50 selection + gather (fused) ----------------
// 4 blocks (one per class), 1024 threads. All NPIX data prefetched into registers.
__global__ __launch_bounds__(1024, 1) void k_select(const float* __restrict__ neg) {
    __shared__ int   hist[NBIN];
    __shared__ int   s_chunk[32];
    __shared__ float cv[MAXCAND];
    __shared__ int   ci[MAXCAND];
    __shared__ int   s_sel[KSEL];
    __shared__ int   s_cnt;
    __shared__ int   s_binThr;

    int s = blockIdx.x;
    int t = threadIdx.x;

    // ---- register prefetch: 8 elements per thread, 4 wide coalesced loads ----
    int  seg[8];
    float pv[8];
    int  bin[8];
    {
        const int4*   ps = (const int4*)(g_seg_neg) + t * 2;
        const float4* pp = (const float4*)(g_neg_prob) + t * 2;
        int4 s0 = ps[0], s1 = ps[1];
        float4 p0 = pp[0], p1 = pp[1];
        seg[0]=s0.x; seg[1]=s0.y; seg[2]=s0.z; seg[3]=s0.w;
        seg[4]=s1.x; seg[5]=s1.y; seg[6]=s1.z; seg[7]=s1.w;
        pv[0]=p0.x; pv[1]=p0.y; pv[2]=p0.z; pv[3]=p0.w;
        pv[4]=p1.x; pv[5]=p1.y; pv[6]=p1.z; pv[7]=p1.w;
        #pragma unroll
        for (int j = 0; j < 8; j++) {
            int b = (int)((pv[j] - 0.25f) * (1024.0f / 0.75f));
            bin[j] = max(0, min(NBIN - 1, b));
        }
    }

    for (int i = t; i < NBIN; i += 1024) hist[i] = 0;
    if (t == 0) s_cnt = 0;
    __syncthreads();

    // ---- histogram from registers ----
    #pragma unroll
    for (int j = 0; j < 8; j++)
        if (seg[j] != s) atomicAdd(&hist[bin[j]], 1);
    __syncthreads();

    // ---- threshold bin ----
    if (t < 32) {
        int sum = 0;
        #pragma unroll
        for (int j = 0; j < 32; j++) sum += hist[t * 32 + j];
        s_chunk[t] = sum;
    }
    __syncthreads();
    if (t == 0) {
        int cum = 0, binThr = 0;
        for (int cb = 31; cb >= 0; cb--) {
            if (cum + s_chunk[cb] >= KSEL) {
                for (int bb = cb * 32 + 31; bb >= cb * 32; bb--) {
                    cum += hist[bb];
                    if (cum >= KSEL) { binThr = bb; break; }
                }
                break;
            }
            cum += s_chunk[cb];
        }
        s_binThr = binThr;
    }
    __syncthreads();
    int binThr = s_binThr;

    // ---- collect candidates from registers ----
    #pragma unroll
    for (int j = 0; j < 8; j++) {
        if (seg[j] != s && bin[j] >= binThr) {
            int pos = atomicAdd(&s_cnt, 1);
            if (pos < MAXCAND) { cv[pos] = pv[j]; ci[pos] = t * 8 + j; }
        }
    }
    __syncthreads();
    int M = min(s_cnt, MAXCAND);

    // ---- exact rank (value desc, index asc tie-break == lax.top_k) ----
    for (int c = t; c < M; c += 1024) {
        float v = cv[c]; int id = ci[c];
        int r = 0;
        for (int m = 0; m < M; m++) {
            float vm = cv[m];
            if (vm > v || (vm == v && ci[m] < id)) r++;
        }
        if (r < KSEL) s_sel[r] = id;
    }
    __syncthreads();

    // ---- fused gather + normalize of the 50 selected negatives ----
    {
        int w = t >> 5, lane = t & 31;     // 32 warps
        for (int k = w; k < KSEL; k += 32) {
            int n = s_sel[k];
            int b = n >> 12, rem = n & 4095;
            const float* p = neg + (size_t)b * CC * HW + rem;
            float v[4]; float ss = 0.f;
            #pragma unroll
            for (int j = 0; j < 4; j++) {
                int c = lane + j * 32;
                v[j] = p[(size_t)c * HW];
                ss += v[j] * v[j];
            }
            #pragma unroll
            for (int off = 16; off; off >>= 1) ss += __shfl_xor_sync(0xffffffffu, ss, off);
            float inv = 1.0f / fmaxf(sqrtf(ss), 1e-12f);
            float* G = (float*)g_G4;
            size_t row = (size_t)(s * KSEL + k) * CC;
            #pragma unroll
            for (int j = 0; j < 4; j++) {
                int c = lane + j * 32;
                G[row + c] = v[j] * inv;
            }
        }
    }
}

// ---------------- kernel 4: main contrastive accumulation ----------------
__global__ void k_main() {
    int warp = threadIdx.x >> 5, lane = threadIdx.x & 31;
    int n = blockIdx.x * 8 + warp;

    float4 x4 = g_inT4[(size_t)n * 32 + lane];
    float4 p4 = g_posT4[(size_t)n * 32 + lane];
    int cls = g_seg_in[n];
    const float4* G = g_G4 + (size_t)cls * KSEL * 32;

    float accN = 0.f, accA = 0.f;
    #pragma unroll 5
    for (int k = 0; k < KSEL; k++) {
        float4 g4 = __ldg(&G[(size_t)k * 32 + lane]);
        float dn = g4.x * x4.x + g4.y * x4.y + g4.z * x4.z + g4.w * x4.w;
        float da = g4.x * p4.x + g4.y * p4.y + g4.z * p4.z + g4.w * p4.w;
        #pragma unroll
        for (int off = 16; off; off >>= 1) {
            dn += __shfl_xor_sync(0xffffffffu, dn, off);
            da += __shfl_xor_sync(0xffffffffu, da, off);
        }
        accN += exp2f(dn * TAUINV_LOG2E);
        accA += exp2f(da * TAUINV_LOG2E);
    }

    float ps  = g_pos_sim[n];
    float nom = exp2f(ps * TAUINV_LOG2E);
    float term = logf(nom / (accN + nom + 1e-8f)) + logf(nom / (accA + nom + 1e-8f));

    __shared__ float sred[8];
    if (lane == 0) sred[warp] = term;
    __syncthreads();
    if (threadIdx.x == 0) {
        float sum = 0.f;
        #pragma unroll
        for (int i = 0; i < 8; i++) sum += sred[i];
        atomicAdd(&g_acc, sum);
    }
}

// ---------------- kernel 5: finalize ----------------
__global__ void k_final(float* __restrict__ out) {
    out[0] = -g_acc / (float)NPIX;
}

// ---------------- launch ----------------
extern "C" void kernel_launch(void* const* d_in, const int* in_sizes, int n_in,
                              void* d_out, int out_size) {
    const float* inp = (const float*)d_in[0];   // input    [2,128,64,64]
    const float* pos = (const float*)d_in[1];   // positive
    const float* neg = (const float*)d_in[2];   // negative
    const float* il  = (const float*)d_in[3];   // input_logits    [2,4,64,64]
    const float* nl  = (const float*)d_in[4];   // negative_logits
    float* out = (float*)d_out;

    k_seg<<<NPIX / 256, 256>>>(il, nl);
    k_norm<<<NPIX / 32, 256>>>(inp, pos);
    k_select<<<NCLS, 1024>>>(neg);
    k_main<<<NPIX / 8, 256>>>();
    k_final<<<1, 1>>>(out);
}